// round 8
// baseline (speedup 1.0000x reference)
#include <cuda_runtime.h>
#include <cuda_bf16.h>

// Problem constants
#define BV     32000
#define EE     256
#define HH     512
#define SS     128
#define TT     64
#define BB     32
#define NSTEP  63
#define H3     1536
#define OUT_PRED (64512000LL)

// ---------------- scratch ----------------------------------------------------
__device__ float g_encW1[4096 * 512];          // enc @ W1
__device__ float g_gxemb[NSTEP * BB * H3];     // emb@Wx_bot + b_g
__device__ float g_h    [NSTEP * BB * HH];     // h_t
__device__ float g_ctx  [BB * HH];             // current context
__device__ float g_p1   [4 * BB * 2560];       // comb GEMM partials: [kc][b][2560]
                                               //   cols 0..1535 = ctx@Wx_top, 1536..2559 = h@Wh_zr
__device__ float g_ph   [4 * BB * HH];         // rh@Wh3 partials
__device__ float g_hw2p [4 * BB * HH];         // h@W2 partials

// ---------------- helpers ----------------------------------------------------
__device__ __forceinline__ unsigned long long dup2(float b) {
    unsigned long long r;
    unsigned int u = __float_as_uint(b);
    asm("mov.b64 %0, {%1, %1};" : "=l"(r) : "r"(u));
    return r;
}
__device__ __forceinline__ void fma2(unsigned long long& d,
                                     unsigned long long a,
                                     unsigned long long b) {
    asm("fma.rn.f32x2 %0, %1, %2, %3;" : "=l"(d) : "l"(a), "l"(b), "l"(d));
}
__device__ __forceinline__ float fast_tanh(float x) {
    float e = __expf(2.0f * x);
    return 1.0f - 2.0f / (e + 1.0f);
}
__device__ __forceinline__ float fast_sig(float x) {
    return 1.0f / (1.0f + __expf(-x));
}
__device__ __forceinline__ float tanh_approx(float x) {
    float y;
    asm("tanh.approx.f32 %0, %1;" : "=f"(y) : "f"(x));
    return y;
}
__device__ __forceinline__ float p1sum(int b, int col) {
    return g_p1[(0 * BB + b) * 2560 + col] + g_p1[(1 * BB + b) * 2560 + col]
         + g_p1[(2 * BB + b) * 2560 + col] + g_p1[(3 * BB + b) * 2560 + col];
}

// ---------------- generic 128x128 tiled fp32 GEMM ----------------------------
// MODE 0: C=g_encW1 : A=enc(4096x512),         B=W1(512x512)
// MODE 1: C=g_gxemb : A=emb[tok(m)](2016x256), B=Wx_bot(256x1536), +b_g
// MODE 2: C=preds   : A=g_h(2016x512),         B=Wo(512x32000), +bo, scatter
template<int MODE>
__global__ __launch_bounds__(256, 2)
void gemm_k(const float* __restrict__ A,  const float* __restrict__ W1,
            const float* __restrict__ Wx, const float* __restrict__ Wo,
            const float* __restrict__ bias,
            const int*   __restrict__ dinp, const int* __restrict__ dtgt,
            const float* __restrict__ emb, float* __restrict__ C,
            int M, int K)
{
    __shared__ __align__(16) float As[16][132];
    __shared__ __align__(16) float Bs[16][132];

    const int tid = threadIdx.x;
    const int tx = tid & 15;
    const int ty = tid >> 4;
    const int bn = blockIdx.x, bm = blockIdx.y;

    unsigned long long acc[4][8];
#pragma unroll
    for (int i = 0; i < 4; i++)
#pragma unroll
        for (int j = 0; j < 8; j++) acc[i][j] = 0ULL;

    const int nTiles = K >> 4;
    for (int kt = 0; kt < nTiles; ++kt) {
#pragma unroll
        for (int q = 0; q < 2; q++) {
            int l = tid * 2 + q;
            int r = l >> 2;
            int cseg = l & 3;
            int rowg = bm * 128 + r; if (rowg > M - 1) rowg = M - 1;
            const float* ap;
            if (MODE == 1) {
                int t = rowg >> 5, b = rowg & 31;
                int tok = (t == 0) ? dinp[b] : dtgt[b * TT + t];
                ap = emb + (long long)tok * EE;
            } else if (MODE == 2) {
                ap = g_h + (long long)rowg * HH;
            } else {
                ap = A + (long long)rowg * K;
            }
            float4 v = *reinterpret_cast<const float4*>(ap + kt * 16 + cseg * 4);
            As[cseg * 4 + 0][r] = v.x; As[cseg * 4 + 1][r] = v.y;
            As[cseg * 4 + 2][r] = v.z; As[cseg * 4 + 3][r] = v.w;
            int kr = l >> 5;
            int nseg = l & 31;
            int kg = kt * 16 + kr;
            int n = bn * 128 + nseg * 4;
            const float* bp;
            if (MODE == 0) {
                bp = W1 + (long long)kg * 512 + n;
            } else if (MODE == 1) {
                bp = Wx + (long long)(512 + kg) * H3 + n;
            } else {
                bp = Wo + (long long)kg * BV + n;
            }
            *reinterpret_cast<float4*>(&Bs[kr][nseg * 4]) =
                *reinterpret_cast<const float4*>(bp);
        }
        __syncthreads();
#pragma unroll
        for (int k = 0; k < 16; k++) {
            const unsigned long long* arow =
                reinterpret_cast<const unsigned long long*>(&As[k][0]);
            unsigned long long a0 = arow[ty * 4 + 0];
            unsigned long long a1 = arow[ty * 4 + 1];
            unsigned long long a2 = arow[ty * 4 + 2];
            unsigned long long a3 = arow[ty * 4 + 3];
            float4 b0 = *reinterpret_cast<const float4*>(&Bs[k][tx * 4]);
            float4 b1 = *reinterpret_cast<const float4*>(&Bs[k][64 + tx * 4]);
            float bf[8] = {b0.x, b0.y, b0.z, b0.w, b1.x, b1.y, b1.z, b1.w};
#pragma unroll
            for (int j = 0; j < 8; j++) {
                unsigned long long dj = dup2(bf[j]);
                fma2(acc[0][j], a0, dj);
                fma2(acc[1][j], a1, dj);
                fma2(acc[2][j], a2, dj);
                fma2(acc[3][j], a3, dj);
            }
        }
        __syncthreads();
    }

    const int nA = bn * 128 + tx * 4;
    const int nB = nA + 64;
#pragma unroll
    for (int i2 = 0; i2 < 4; i2++) {
#pragma unroll
        for (int p = 0; p < 2; p++) {
            int m = bm * 128 + ty * 8 + i2 * 2 + p;
            if (m >= M) continue;
            float vals[8];
#pragma unroll
            for (int j = 0; j < 8; j++) {
                unsigned long long u = acc[i2][j];
                unsigned int w = (p == 0) ? (unsigned int)u
                                          : (unsigned int)(u >> 32);
                vals[j] = __uint_as_float(w);
            }
            if (MODE == 0) {
                float* cp = g_encW1 + (long long)m * 512;
                *reinterpret_cast<float4*>(cp + nA) =
                    make_float4(vals[0], vals[1], vals[2], vals[3]);
                *reinterpret_cast<float4*>(cp + nB) =
                    make_float4(vals[4], vals[5], vals[6], vals[7]);
            } else if (MODE == 1) {
                float* cp = g_gxemb + (long long)m * H3;
                float4 ba = *reinterpret_cast<const float4*>(bias + nA);
                float4 bb = *reinterpret_cast<const float4*>(bias + nB);
                *reinterpret_cast<float4*>(cp + nA) =
                    make_float4(vals[0] + ba.x, vals[1] + ba.y,
                                vals[2] + ba.z, vals[3] + ba.w);
                *reinterpret_cast<float4*>(cp + nB) =
                    make_float4(vals[4] + bb.x, vals[5] + bb.y,
                                vals[6] + bb.z, vals[7] + bb.w);
            } else {
                int t = m >> 5, b = m & 31;
                float* cp = C + (long long)b * (NSTEP * (long long)BV)
                              + (long long)t * BV;
                float4 ba = *reinterpret_cast<const float4*>(bias + nA);
                float4 bb = *reinterpret_cast<const float4*>(bias + nB);
                *reinterpret_cast<float4*>(cp + nA) =
                    make_float4(vals[0] + ba.x, vals[1] + ba.y,
                                vals[2] + ba.z, vals[3] + ba.w);
                *reinterpret_cast<float4*>(cp + nB) =
                    make_float4(vals[4] + bb.x, vals[5] + bb.y,
                                vals[6] + bb.z, vals[7] + bb.w);
            }
        }
    }
}

// ---------------- K1: combined GEMM partials --------------------------------
// cols 0..1535: gx_top = ctx @ Wx[0:512,:]   (A = g_ctx)
// cols 1536..2559: ghzr = h_prev @ Wh[:,0:1024]  (A = h_prev)
// grid (4 kc, 20 bc), 256 thr; weights read once; FMA2 over batch pairs.
__global__ __launch_bounds__(256)
void k_comb(const float* __restrict__ dec_hidden,
            const float* __restrict__ Wx,
            const float* __restrict__ Wh, int t)
{
    const int kc = blockIdx.x, bc = blockIdx.y;
    const int kbase = kc * 128;
    const int tid = threadIdx.x;
    const float* hprev = (t == 0) ? dec_hidden
                                  : g_h + (long long)(t - 1) * BB * HH;
    const float* Asrc = (bc < 12) ? g_ctx : hprev;

    __shared__ float hT[128 * 34];
    for (int i = tid; i < 4096; i += 256) {
        int b = i >> 7, k = i & 127;
        hT[k * 34 + b] = Asrc[b * HH + kbase + k];
    }
    __syncthreads();

    const int cq = tid & 31;
    const int bq = tid >> 5;
    const int c0 = bc * 128 + cq * 4;
    const float* wrow = (bc < 12) ? (Wx + c0) : (Wh + (c0 - 1536));

    unsigned long long acc[4][2];
#pragma unroll
    for (int c = 0; c < 4; c++) { acc[c][0] = 0ULL; acc[c][1] = 0ULL; }

#pragma unroll 4
    for (int k = 0; k < 128; k++) {
        float4 w = *reinterpret_cast<const float4*>(
            wrow + (long long)(kbase + k) * H3);
        unsigned long long h01 =
            *reinterpret_cast<const unsigned long long*>(&hT[k * 34 + bq * 4]);
        unsigned long long h23 =
            *reinterpret_cast<const unsigned long long*>(&hT[k * 34 + bq * 4 + 2]);
        unsigned long long w0 = dup2(w.x), w1 = dup2(w.y),
                           w2 = dup2(w.z), w3 = dup2(w.w);
        fma2(acc[0][0], h01, w0); fma2(acc[0][1], h23, w0);
        fma2(acc[1][0], h01, w1); fma2(acc[1][1], h23, w1);
        fma2(acc[2][0], h01, w2); fma2(acc[2][1], h23, w2);
        fma2(acc[3][0], h01, w3); fma2(acc[3][1], h23, w3);
    }
#pragma unroll
    for (int c = 0; c < 4; c++)
#pragma unroll
        for (int p = 0; p < 2; p++) {
            int b = bq * 4 + p * 2;
            unsigned long long u = acc[c][p];
            g_p1[(kc * BB + b)     * 2560 + c0 + c] =
                __uint_as_float((unsigned int)u);
            g_p1[(kc * BB + b + 1) * 2560 + c0 + c] =
                __uint_as_float((unsigned int)(u >> 32));
        }
}

// ---------------- K2: rh gates + rh@Wh3 partials ----------------------------
// grid (4 kc, 4 bc). Prologue: rh = sigmoid(gx_r + ghzr_r) * h_prev for the
// block's k-slice; then GEMV partials over Wh[:,1024:].
__global__ __launch_bounds__(256)
void k_hh3(const float* __restrict__ dec_hidden,
           const float* __restrict__ Wh, int t)
{
    const int kc = blockIdx.x, bc = blockIdx.y;
    const int kbase = kc * 128;
    const int tid = threadIdx.x;
    const float* hprev = (t == 0) ? dec_hidden
                                  : g_h + (long long)(t - 1) * BB * HH;

    __shared__ float hT[128 * 34];
    for (int i = tid; i < 4096; i += 256) {
        int b = i >> 7, k = i & 127;
        int kk = kbase + k;
        float g = p1sum(b, 512 + kk)
                + g_gxemb[((long long)t * BB + b) * H3 + 512 + kk]
                + p1sum(b, 2048 + kk);
        hT[k * 34 + b] = fast_sig(g) * hprev[b * HH + kk];
    }
    __syncthreads();

    const int cq = tid & 31;
    const int bq = tid >> 5;
    const int c0 = bc * 128 + cq * 4;
    const float* wrow = Wh + 1024 + c0;

    unsigned long long acc[4][2];
#pragma unroll
    for (int c = 0; c < 4; c++) { acc[c][0] = 0ULL; acc[c][1] = 0ULL; }

#pragma unroll 4
    for (int k = 0; k < 128; k++) {
        float4 w = *reinterpret_cast<const float4*>(
            wrow + (long long)(kbase + k) * H3);
        unsigned long long h01 =
            *reinterpret_cast<const unsigned long long*>(&hT[k * 34 + bq * 4]);
        unsigned long long h23 =
            *reinterpret_cast<const unsigned long long*>(&hT[k * 34 + bq * 4 + 2]);
        unsigned long long w0 = dup2(w.x), w1 = dup2(w.y),
                           w2 = dup2(w.z), w3 = dup2(w.w);
        fma2(acc[0][0], h01, w0); fma2(acc[0][1], h23, w0);
        fma2(acc[1][0], h01, w1); fma2(acc[1][1], h23, w1);
        fma2(acc[2][0], h01, w2); fma2(acc[2][1], h23, w2);
        fma2(acc[3][0], h01, w3); fma2(acc[3][1], h23, w3);
    }
#pragma unroll
    for (int c = 0; c < 4; c++)
#pragma unroll
        for (int p = 0; p < 2; p++) {
            int b = bq * 4 + p * 2;
            unsigned long long u = acc[c][p];
            g_ph[(kc * BB + b)     * HH + c0 + c] =
                __uint_as_float((unsigned int)u);
            g_ph[(kc * BB + b + 1) * HH + c0 + c] =
                __uint_as_float((unsigned int)(u >> 32));
        }
}

// ---------------- K3: z gate, candidate tanh, blend -> h_t ------------------
__global__ void k_blend(const float* __restrict__ dec_hidden, int t)
{
    int b = blockIdx.x;
    int c = threadIdx.x;
    const float* hprev = (t == 0) ? dec_hidden
                                  : g_h + (long long)(t - 1) * BB * HH;
    const float* ge = g_gxemb + ((long long)t * BB + b) * H3;
    float z   = fast_sig(p1sum(b, c) + ge[c] + p1sum(b, 1536 + c));
    float gx3 = p1sum(b, 1024 + c) + ge[1024 + c];
    float hs  = g_ph[(0 * BB + b) * HH + c] + g_ph[(1 * BB + b) * HH + c]
              + g_ph[(2 * BB + b) * HH + c] + g_ph[(3 * BB + b) * HH + c];
    float hh  = fast_tanh(gx3 + hs);
    float hp  = hprev[b * HH + c];
    g_h[((long long)t * BB + b) * HH + c] = z * hp + (1.f - z) * hh;
}

// ---------------- K4: hW2 = h @ W2 partials ---------------------------------
// grid (4 kc, 4 bc). t = -1 -> h = dec_hidden, else h = g_h[t].
__global__ __launch_bounds__(256)
void k_hw2(const float* __restrict__ dec_hidden,
           const float* __restrict__ W2, int t)
{
    const int kc = blockIdx.x, bc = blockIdx.y;
    const int kbase = kc * 128;
    const int tid = threadIdx.x;
    const float* hsrc = (t < 0) ? dec_hidden
                                : g_h + (long long)t * BB * HH;

    __shared__ float hT[128 * 34];
    for (int i = tid; i < 4096; i += 256) {
        int b = i >> 7, k = i & 127;
        hT[k * 34 + b] = hsrc[b * HH + kbase + k];
    }
    __syncthreads();

    const int cq = tid & 31;
    const int bq = tid >> 5;
    const int c0 = bc * 128 + cq * 4;
    const float* wrow = W2 + c0;

    unsigned long long acc[4][2];
#pragma unroll
    for (int c = 0; c < 4; c++) { acc[c][0] = 0ULL; acc[c][1] = 0ULL; }

#pragma unroll 4
    for (int k = 0; k < 128; k++) {
        float4 w = *reinterpret_cast<const float4*>(
            wrow + (long long)(kbase + k) * 512);
        unsigned long long h01 =
            *reinterpret_cast<const unsigned long long*>(&hT[k * 34 + bq * 4]);
        unsigned long long h23 =
            *reinterpret_cast<const unsigned long long*>(&hT[k * 34 + bq * 4 + 2]);
        unsigned long long w0 = dup2(w.x), w1 = dup2(w.y),
                           w2 = dup2(w.z), w3 = dup2(w.w);
        fma2(acc[0][0], h01, w0); fma2(acc[0][1], h23, w0);
        fma2(acc[1][0], h01, w1); fma2(acc[1][1], h23, w1);
        fma2(acc[2][0], h01, w2); fma2(acc[2][1], h23, w2);
        fma2(acc[3][0], h01, w3); fma2(acc[3][1], h23, w3);
    }
#pragma unroll
    for (int c = 0; c < 4; c++)
#pragma unroll
        for (int p = 0; p < 2; p++) {
            int b = bq * 4 + p * 2;
            unsigned long long u = acc[c][p];
            g_hw2p[(kc * BB + b)     * HH + c0 + c] =
                __uint_as_float((unsigned int)u);
            g_hw2p[(kc * BB + b + 1) * HH + c0 + c] =
                __uint_as_float((unsigned int)(u >> 32));
        }
}

// ---------------- K5: score + softmax + ctx ---------------------------------
// grid 32 (one block per batch), 256 thr.
__global__ __launch_bounds__(256)
void k_ctx(const float* __restrict__ enc,
           const float* __restrict__ v_a)
{
    const int b = blockIdx.x;
    const int tid = threadIdx.x;
    __shared__ float hv[HH];
    __shared__ float vv[HH];
    __shared__ float sc[SS];
    __shared__ float red[SS];
    __shared__ float at[SS];

    for (int i = tid; i < HH; i += 256) {
        hv[i] = g_hw2p[(0 * BB + b) * HH + i] + g_hw2p[(1 * BB + b) * HH + i]
              + g_hw2p[(2 * BB + b) * HH + i] + g_hw2p[(3 * BB + b) * HH + i];
        vv[i] = v_a[i];
    }
    __syncthreads();

    {
        int warp = tid >> 5, lane = tid & 31;
        for (int s = warp; s < SS; s += 8) {
            const float* e = g_encW1 + ((long long)(b * SS + s)) * 512;
            float sum = 0.f;
#pragma unroll
            for (int i = 0; i < 16; i++) {
                int a = i * 32 + lane;
                sum += tanh_approx(e[a] + hv[a]) * vv[a];
            }
#pragma unroll
            for (int o = 16; o > 0; o >>= 1)
                sum += __shfl_xor_sync(0xffffffffu, sum, o);
            if (lane == 0) sc[s] = sum;
        }
    }
    __syncthreads();

    if (tid < SS) red[tid] = sc[tid];
    __syncthreads();
    for (int o = 64; o > 0; o >>= 1) {
        if (tid < o) red[tid] = fmaxf(red[tid], red[tid + o]);
        __syncthreads();
    }
    float mx = red[0];
    __syncthreads();
    if (tid < SS) red[tid] = __expf(sc[tid] - mx);
    __syncthreads();
    for (int o = 64; o > 0; o >>= 1) {
        if (tid < o) red[tid] += red[tid + o];
        __syncthreads();
    }
    float ssum = red[0];
    __syncthreads();
    if (tid < SS) at[tid] = __expf(sc[tid] - mx) / ssum;
    __syncthreads();

    // ctx[b,c] = sum_s at[s] * enc[b,s,c]
    for (int c = tid; c < HH; c += 256) {
        const float* ep = enc + ((long long)b * SS) * HH + c;
        float acc = 0.f;
#pragma unroll 8
        for (int s = 0; s < SS; s++) acc += at[s] * ep[(long long)s * HH];
        g_ctx[b * HH + c] = acc;
    }
}

// final hidden state copy
__global__ void k_copyh(float* __restrict__ out)
{
    int i = blockIdx.x * 256 + threadIdx.x;
    out[i] = g_h[(long long)(NSTEP - 1) * BB * HH + i];
}

extern "C" void kernel_launch(void* const* d_in, const int* in_sizes, int n_in,
                              void* d_out, int out_size)
{
    const int*   dec_input  = (const int*)  d_in[0];
    const float* dec_hidden = (const float*)d_in[1];
    const float* enc_output = (const float*)d_in[2];
    const int*   dec_target = (const int*)  d_in[3];
    const float* embedding  = (const float*)d_in[4];
    const float* W1  = (const float*)d_in[5];
    const float* W2  = (const float*)d_in[6];
    const float* v_a = (const float*)d_in[7];
    const float* Wx  = (const float*)d_in[8];
    const float* Wh  = (const float*)d_in[9];
    const float* b_g = (const float*)d_in[10];
    const float* Wo  = (const float*)d_in[11];
    const float* bo  = (const float*)d_in[12];
    float* out = (float*)d_out;

    // Precompute: encW1 = enc @ W1 (4096x512, K=512)
    gemm_k<0><<<dim3(4, 32), 256>>>(enc_output, W1, Wx, nullptr, nullptr,
                                    nullptr, nullptr, nullptr, nullptr,
                                    4096, 512);
    // Precompute: gxemb = emb[tok] @ Wx_bot + b_g (2016x1536, K=256)
    gemm_k<1><<<dim3(12, 16), 256>>>(nullptr, nullptr, Wx, nullptr, b_g,
                                     dec_input, dec_target, embedding, nullptr,
                                     2016, 256);
    // Initial attention context from dec_hidden
    k_hw2<<<dim3(4, 4), 256>>>(dec_hidden, W2, -1);
    k_ctx<<<32, 256>>>(enc_output, v_a);

    // Recurrence: 63 steps
    for (int t = 0; t < NSTEP; t++) {
        k_comb <<<dim3(4, 20), 256>>>(dec_hidden, Wx, Wh, t);
        k_hh3  <<<dim3(4, 4), 256>>>(dec_hidden, Wh, t);
        k_blend<<<32, 512>>>(dec_hidden, t);
        if (t < NSTEP - 1) {          // ctx for next step
            k_hw2<<<dim3(4, 4), 256>>>(dec_hidden, W2, t);
            k_ctx<<<32, 256>>>(enc_output, v_a);
        }
    }
    // Deferred pred GEMM (2016x32000, K=512)
    gemm_k<2><<<dim3(250, 16), 256>>>(nullptr, nullptr, nullptr, Wo, bo,
                                      nullptr, nullptr, nullptr, out,
                                      2016, 512);
    if ((long long)out_size >= OUT_PRED + BB * HH)
        k_copyh<<<64, 256>>>(out + OUT_PRED);
}

// round 9
// speedup vs baseline: 1.1626x; 1.1626x over previous
#include <cuda_runtime.h>
#include <cuda_bf16.h>

// Problem constants
#define BV     32000
#define EE     256
#define HH     512
#define SS     128
#define TT     64
#define BB     32
#define NSTEP  63
#define H3     1536
#define OUT_PRED (64512000LL)

// ---------------- scratch ----------------------------------------------------
__device__ float g_encW1[4096 * 512];          // enc @ W1
__device__ float g_gxemb[NSTEP * BB * H3];     // emb@Wx_bot + b_g
__device__ float g_h    [NSTEP * BB * HH];     // h_t
__device__ float g_ctx  [BB * HH];             // current context
__device__ float g_score[BB * SS];             // attention scores
__device__ float g_p1   [4 * BB * 2560];       // comb partials: [kc][b][2560]
                                               //   0..1535 = ctx@Wx_top, 1536..2559 = h@Wh_zr
__device__ float g_ph   [4 * BB * HH];         // rh@Wh3 partials
__device__ float g_hw2p [4 * BB * HH];         // h@W2 partials

// ---------------- helpers ----------------------------------------------------
__device__ __forceinline__ unsigned long long dup2(float b) {
    unsigned long long r;
    unsigned int u = __float_as_uint(b);
    asm("mov.b64 %0, {%1, %1};" : "=l"(r) : "r"(u));
    return r;
}
__device__ __forceinline__ void fma2(unsigned long long& d,
                                     unsigned long long a,
                                     unsigned long long b) {
    asm("fma.rn.f32x2 %0, %1, %2, %3;" : "=l"(d) : "l"(a), "l"(b), "l"(d));
}
__device__ __forceinline__ float fast_tanh(float x) {
    float e = __expf(2.0f * x);
    return 1.0f - 2.0f / (e + 1.0f);
}
__device__ __forceinline__ float fast_sig(float x) {
    return 1.0f / (1.0f + __expf(-x));
}
__device__ __forceinline__ float tanh_approx(float x) {
    float y;
    asm("tanh.approx.f32 %0, %1;" : "=f"(y) : "f"(x));
    return y;
}
__device__ __forceinline__ float p1sum(int b, int col) {
    return g_p1[(0 * BB + b) * 2560 + col] + g_p1[(1 * BB + b) * 2560 + col]
         + g_p1[(2 * BB + b) * 2560 + col] + g_p1[(3 * BB + b) * 2560 + col];
}

// ---------------- generic 128x128 tiled fp32 GEMM ----------------------------
// MODE 0: C=g_encW1 : A=enc(4096x512),         B=W1(512x512)
// MODE 1: C=g_gxemb : A=emb[tok(m)](2016x256), B=Wx_bot(256x1536), +b_g
// MODE 2: C=preds   : A=g_h(2016x512),         B=Wo(512x32000), +bo, scatter
template<int MODE>
__global__ __launch_bounds__(256, 2)
void gemm_k(const float* __restrict__ A,  const float* __restrict__ W1,
            const float* __restrict__ Wx, const float* __restrict__ Wo,
            const float* __restrict__ bias,
            const int*   __restrict__ dinp, const int* __restrict__ dtgt,
            const float* __restrict__ emb, float* __restrict__ C,
            int M, int K)
{
    __shared__ __align__(16) float As[16][132];
    __shared__ __align__(16) float Bs[16][132];

    const int tid = threadIdx.x;
    const int tx = tid & 15;
    const int ty = tid >> 4;
    const int bn = blockIdx.x, bm = blockIdx.y;

    unsigned long long acc[4][8];
#pragma unroll
    for (int i = 0; i < 4; i++)
#pragma unroll
        for (int j = 0; j < 8; j++) acc[i][j] = 0ULL;

    const int nTiles = K >> 4;
    for (int kt = 0; kt < nTiles; ++kt) {
#pragma unroll
        for (int q = 0; q < 2; q++) {
            int l = tid * 2 + q;
            int r = l >> 2;
            int cseg = l & 3;
            int rowg = bm * 128 + r; if (rowg > M - 1) rowg = M - 1;
            const float* ap;
            if (MODE == 1) {
                int t = rowg >> 5, b = rowg & 31;
                int tok = (t == 0) ? dinp[b] : dtgt[b * TT + t];
                ap = emb + (long long)tok * EE;
            } else if (MODE == 2) {
                ap = g_h + (long long)rowg * HH;
            } else {
                ap = A + (long long)rowg * K;
            }
            float4 v = *reinterpret_cast<const float4*>(ap + kt * 16 + cseg * 4);
            As[cseg * 4 + 0][r] = v.x; As[cseg * 4 + 1][r] = v.y;
            As[cseg * 4 + 2][r] = v.z; As[cseg * 4 + 3][r] = v.w;
            int kr = l >> 5;
            int nseg = l & 31;
            int kg = kt * 16 + kr;
            int n = bn * 128 + nseg * 4;
            const float* bp;
            if (MODE == 0) {
                bp = W1 + (long long)kg * 512 + n;
            } else if (MODE == 1) {
                bp = Wx + (long long)(512 + kg) * H3 + n;
            } else {
                bp = Wo + (long long)kg * BV + n;
            }
            *reinterpret_cast<float4*>(&Bs[kr][nseg * 4]) =
                *reinterpret_cast<const float4*>(bp);
        }
        __syncthreads();
#pragma unroll
        for (int k = 0; k < 16; k++) {
            const unsigned long long* arow =
                reinterpret_cast<const unsigned long long*>(&As[k][0]);
            unsigned long long a0 = arow[ty * 4 + 0];
            unsigned long long a1 = arow[ty * 4 + 1];
            unsigned long long a2 = arow[ty * 4 + 2];
            unsigned long long a3 = arow[ty * 4 + 3];
            float4 b0 = *reinterpret_cast<const float4*>(&Bs[k][tx * 4]);
            float4 b1 = *reinterpret_cast<const float4*>(&Bs[k][64 + tx * 4]);
            float bf[8] = {b0.x, b0.y, b0.z, b0.w, b1.x, b1.y, b1.z, b1.w};
#pragma unroll
            for (int j = 0; j < 8; j++) {
                unsigned long long dj = dup2(bf[j]);
                fma2(acc[0][j], a0, dj);
                fma2(acc[1][j], a1, dj);
                fma2(acc[2][j], a2, dj);
                fma2(acc[3][j], a3, dj);
            }
        }
        __syncthreads();
    }

    const int nA = bn * 128 + tx * 4;
    const int nB = nA + 64;
#pragma unroll
    for (int i2 = 0; i2 < 4; i2++) {
#pragma unroll
        for (int p = 0; p < 2; p++) {
            int m = bm * 128 + ty * 8 + i2 * 2 + p;
            if (m >= M) continue;
            float vals[8];
#pragma unroll
            for (int j = 0; j < 8; j++) {
                unsigned long long u = acc[i2][j];
                unsigned int w = (p == 0) ? (unsigned int)u
                                          : (unsigned int)(u >> 32);
                vals[j] = __uint_as_float(w);
            }
            if (MODE == 0) {
                float* cp = g_encW1 + (long long)m * 512;
                *reinterpret_cast<float4*>(cp + nA) =
                    make_float4(vals[0], vals[1], vals[2], vals[3]);
                *reinterpret_cast<float4*>(cp + nB) =
                    make_float4(vals[4], vals[5], vals[6], vals[7]);
            } else if (MODE == 1) {
                float* cp = g_gxemb + (long long)m * H3;
                float4 ba = *reinterpret_cast<const float4*>(bias + nA);
                float4 bb = *reinterpret_cast<const float4*>(bias + nB);
                *reinterpret_cast<float4*>(cp + nA) =
                    make_float4(vals[0] + ba.x, vals[1] + ba.y,
                                vals[2] + ba.z, vals[3] + ba.w);
                *reinterpret_cast<float4*>(cp + nB) =
                    make_float4(vals[4] + bb.x, vals[5] + bb.y,
                                vals[6] + bb.z, vals[7] + bb.w);
            } else {
                int t = m >> 5, b = m & 31;
                float* cp = C + (long long)b * (NSTEP * (long long)BV)
                              + (long long)t * BV;
                float4 ba = *reinterpret_cast<const float4*>(bias + nA);
                float4 bb = *reinterpret_cast<const float4*>(bias + nB);
                *reinterpret_cast<float4*>(cp + nA) =
                    make_float4(vals[0] + ba.x, vals[1] + ba.y,
                                vals[2] + ba.z, vals[3] + ba.w);
                *reinterpret_cast<float4*>(cp + nB) =
                    make_float4(vals[4] + bb.x, vals[5] + bb.y,
                                vals[6] + bb.z, vals[7] + bb.w);
            }
        }
    }
}

// ---------------- K1: combined GEMM partials --------------------------------
// cols 0..1535: gx_top = ctx @ Wx[0:512,:]; cols 1536..2559: h_prev @ Wh[:,0:1024]
__global__ __launch_bounds__(256)
void k_comb(const float* __restrict__ dec_hidden,
            const float* __restrict__ Wx,
            const float* __restrict__ Wh, int t)
{
    const int kc = blockIdx.x, bc = blockIdx.y;
    const int kbase = kc * 128;
    const int tid = threadIdx.x;
    const float* hprev = (t == 0) ? dec_hidden
                                  : g_h + (long long)(t - 1) * BB * HH;
    const float* Asrc = (bc < 12) ? g_ctx : hprev;

    __shared__ float hT[128 * 34];
    for (int i = tid; i < 4096; i += 256) {
        int b = i >> 7, k = i & 127;
        hT[k * 34 + b] = Asrc[b * HH + kbase + k];
    }
    __syncthreads();

    const int cq = tid & 31;
    const int bq = tid >> 5;
    const int c0 = bc * 128 + cq * 4;
    const float* wrow = (bc < 12) ? (Wx + c0) : (Wh + (c0 - 1536));

    unsigned long long acc[4][2];
#pragma unroll
    for (int c = 0; c < 4; c++) { acc[c][0] = 0ULL; acc[c][1] = 0ULL; }

#pragma unroll 4
    for (int k = 0; k < 128; k++) {
        float4 w = *reinterpret_cast<const float4*>(
            wrow + (long long)(kbase + k) * H3);
        unsigned long long h01 =
            *reinterpret_cast<const unsigned long long*>(&hT[k * 34 + bq * 4]);
        unsigned long long h23 =
            *reinterpret_cast<const unsigned long long*>(&hT[k * 34 + bq * 4 + 2]);
        unsigned long long w0 = dup2(w.x), w1 = dup2(w.y),
                           w2 = dup2(w.z), w3 = dup2(w.w);
        fma2(acc[0][0], h01, w0); fma2(acc[0][1], h23, w0);
        fma2(acc[1][0], h01, w1); fma2(acc[1][1], h23, w1);
        fma2(acc[2][0], h01, w2); fma2(acc[2][1], h23, w2);
        fma2(acc[3][0], h01, w3); fma2(acc[3][1], h23, w3);
    }
#pragma unroll
    for (int c = 0; c < 4; c++)
#pragma unroll
        for (int p = 0; p < 2; p++) {
            int b = bq * 4 + p * 2;
            unsigned long long u = acc[c][p];
            g_p1[(kc * BB + b)     * 2560 + c0 + c] =
                __uint_as_float((unsigned int)u);
            g_p1[(kc * BB + b + 1) * 2560 + c0 + c] =
                __uint_as_float((unsigned int)(u >> 32));
        }
}

// ---------------- K2: rh gates + rh@Wh3 partials ----------------------------
__global__ __launch_bounds__(256)
void k_hh3(const float* __restrict__ dec_hidden,
           const float* __restrict__ Wh, int t)
{
    const int kc = blockIdx.x, bc = blockIdx.y;
    const int kbase = kc * 128;
    const int tid = threadIdx.x;
    const float* hprev = (t == 0) ? dec_hidden
                                  : g_h + (long long)(t - 1) * BB * HH;

    __shared__ float hT[128 * 34];
    for (int i = tid; i < 4096; i += 256) {
        int b = i >> 7, k = i & 127;
        int kk = kbase + k;
        float g = p1sum(b, 512 + kk)
                + g_gxemb[((long long)t * BB + b) * H3 + 512 + kk]
                + p1sum(b, 2048 + kk);
        hT[k * 34 + b] = fast_sig(g) * hprev[b * HH + kk];
    }
    __syncthreads();

    const int cq = tid & 31;
    const int bq = tid >> 5;
    const int c0 = bc * 128 + cq * 4;
    const float* wrow = Wh + 1024 + c0;

    unsigned long long acc[4][2];
#pragma unroll
    for (int c = 0; c < 4; c++) { acc[c][0] = 0ULL; acc[c][1] = 0ULL; }

#pragma unroll 4
    for (int k = 0; k < 128; k++) {
        float4 w = *reinterpret_cast<const float4*>(
            wrow + (long long)(kbase + k) * H3);
        unsigned long long h01 =
            *reinterpret_cast<const unsigned long long*>(&hT[k * 34 + bq * 4]);
        unsigned long long h23 =
            *reinterpret_cast<const unsigned long long*>(&hT[k * 34 + bq * 4 + 2]);
        unsigned long long w0 = dup2(w.x), w1 = dup2(w.y),
                           w2 = dup2(w.z), w3 = dup2(w.w);
        fma2(acc[0][0], h01, w0); fma2(acc[0][1], h23, w0);
        fma2(acc[1][0], h01, w1); fma2(acc[1][1], h23, w1);
        fma2(acc[2][0], h01, w2); fma2(acc[2][1], h23, w2);
        fma2(acc[3][0], h01, w3); fma2(acc[3][1], h23, w3);
    }
#pragma unroll
    for (int c = 0; c < 4; c++)
#pragma unroll
        for (int p = 0; p < 2; p++) {
            int b = bq * 4 + p * 2;
            unsigned long long u = acc[c][p];
            g_ph[(kc * BB + b)     * HH + c0 + c] =
                __uint_as_float((unsigned int)u);
            g_ph[(kc * BB + b + 1) * HH + c0 + c] =
                __uint_as_float((unsigned int)(u >> 32));
        }
}

// ---------------- K3: z gate, candidate tanh, blend -> h_t ------------------
__global__ void k_blend(const float* __restrict__ dec_hidden, int t)
{
    int b = blockIdx.x;
    int c = threadIdx.x;
    const float* hprev = (t == 0) ? dec_hidden
                                  : g_h + (long long)(t - 1) * BB * HH;
    const float* ge = g_gxemb + ((long long)t * BB + b) * H3;
    float z   = fast_sig(p1sum(b, c) + ge[c] + p1sum(b, 1536 + c));
    float gx3 = p1sum(b, 1024 + c) + ge[1024 + c];
    float hs  = g_ph[(0 * BB + b) * HH + c] + g_ph[(1 * BB + b) * HH + c]
              + g_ph[(2 * BB + b) * HH + c] + g_ph[(3 * BB + b) * HH + c];
    float hh  = fast_tanh(gx3 + hs);
    float hp  = hprev[b * HH + c];
    g_h[((long long)t * BB + b) * HH + c] = z * hp + (1.f - z) * hh;
}

// ---------------- K4: hW2 = h @ W2 partials ---------------------------------
__global__ __launch_bounds__(256)
void k_hw2(const float* __restrict__ dec_hidden,
           const float* __restrict__ W2, int t)
{
    const int kc = blockIdx.x, bc = blockIdx.y;
    const int kbase = kc * 128;
    const int tid = threadIdx.x;
    const float* hsrc = (t < 0) ? dec_hidden
                                : g_h + (long long)t * BB * HH;

    __shared__ float hT[128 * 34];
    for (int i = tid; i < 4096; i += 256) {
        int b = i >> 7, k = i & 127;
        hT[k * 34 + b] = hsrc[b * HH + kbase + k];
    }
    __syncthreads();

    const int cq = tid & 31;
    const int bq = tid >> 5;
    const int c0 = bc * 128 + cq * 4;
    const float* wrow = W2 + c0;

    unsigned long long acc[4][2];
#pragma unroll
    for (int c = 0; c < 4; c++) { acc[c][0] = 0ULL; acc[c][1] = 0ULL; }

#pragma unroll 4
    for (int k = 0; k < 128; k++) {
        float4 w = *reinterpret_cast<const float4*>(
            wrow + (long long)(kbase + k) * 512);
        unsigned long long h01 =
            *reinterpret_cast<const unsigned long long*>(&hT[k * 34 + bq * 4]);
        unsigned long long h23 =
            *reinterpret_cast<const unsigned long long*>(&hT[k * 34 + bq * 4 + 2]);
        unsigned long long w0 = dup2(w.x), w1 = dup2(w.y),
                           w2 = dup2(w.z), w3 = dup2(w.w);
        fma2(acc[0][0], h01, w0); fma2(acc[0][1], h23, w0);
        fma2(acc[1][0], h01, w1); fma2(acc[1][1], h23, w1);
        fma2(acc[2][0], h01, w2); fma2(acc[2][1], h23, w2);
        fma2(acc[3][0], h01, w3); fma2(acc[3][1], h23, w3);
    }
#pragma unroll
    for (int c = 0; c < 4; c++)
#pragma unroll
        for (int p = 0; p < 2; p++) {
            int b = bq * 4 + p * 2;
            unsigned long long u = acc[c][p];
            g_hw2p[(kc * BB + b)     * HH + c0 + c] =
                __uint_as_float((unsigned int)u);
            g_hw2p[(kc * BB + b + 1) * HH + c0 + c] =
                __uint_as_float((unsigned int)(u >> 32));
        }
}

// ---------------- K5: scores (512 blocks: 16 s-chunks x 32 b) ---------------
__global__ __launch_bounds__(256)
void k_score(const float* __restrict__ v_a)
{
    const int b = blockIdx.y;
    const int schunk = blockIdx.x;          // 0..15 -> 8 s per block
    const int tid = threadIdx.x;
    __shared__ float hv[HH], vv[HH];
    for (int i = tid; i < HH; i += 256) {
        hv[i] = g_hw2p[(0 * BB + b) * HH + i] + g_hw2p[(1 * BB + b) * HH + i]
              + g_hw2p[(2 * BB + b) * HH + i] + g_hw2p[(3 * BB + b) * HH + i];
        vv[i] = v_a[i];
    }
    __syncthreads();
    int warp = tid >> 5, lane = tid & 31;
    int s = schunk * 8 + warp;
    const float* e = g_encW1 + ((long long)(b * SS + s)) * 512;
    float sum = 0.f;
#pragma unroll
    for (int i = 0; i < 16; i++) {
        int a = i * 32 + lane;
        sum += tanh_approx(e[a] + hv[a]) * vv[a];
    }
#pragma unroll
    for (int o = 16; o > 0; o >>= 1)
        sum += __shfl_xor_sync(0xffffffffu, sum, o);
    if (lane == 0) g_score[b * SS + s] = sum;
}

// ---------------- K6: softmax (redundant per c-chunk) + ctx -----------------
// grid (4 cc, 32 b), 256 thr; 2 threads per column, 64 s each.
__global__ __launch_bounds__(256)
void k_softctx(const float* __restrict__ enc)
{
    const int cc = blockIdx.x;
    const int b  = blockIdx.y;
    const int tid = threadIdx.x;
    __shared__ float at[SS];
    __shared__ float red[SS];
    __shared__ float part[256];

    float sc = (tid < SS) ? g_score[b * SS + tid] : -1e30f;
    if (tid < SS) red[tid] = sc;
    __syncthreads();
    for (int o = 64; o > 0; o >>= 1) {
        if (tid < o) red[tid] = fmaxf(red[tid], red[tid + o]);
        __syncthreads();
    }
    float mx = red[0];
    __syncthreads();
    if (tid < SS) red[tid] = __expf(sc - mx);
    __syncthreads();
    for (int o = 64; o > 0; o >>= 1) {
        if (tid < o) red[tid] += red[tid + o];
        __syncthreads();
    }
    float ssum = red[0];
    __syncthreads();
    if (tid < SS) at[tid] = __expf(sc - mx) / ssum;
    __syncthreads();

    const int c = cc * 128 + (tid & 127);
    const int shalf = tid >> 7;             // 0 or 1
    const float* ep = enc + ((long long)(b * SS + shalf * 64)) * HH + c;
    float acc = 0.f;
#pragma unroll 8
    for (int s = 0; s < 64; s++)
        acc += at[shalf * 64 + s] * ep[(long long)s * HH];
    part[tid] = acc;
    __syncthreads();
    if (shalf == 0)
        g_ctx[b * HH + c] = part[tid] + part[tid + 128];
}

// final hidden state copy
__global__ void k_copyh(float* __restrict__ out)
{
    int i = blockIdx.x * 256 + threadIdx.x;
    out[i] = g_h[(long long)(NSTEP - 1) * BB * HH + i];
}

extern "C" void kernel_launch(void* const* d_in, const int* in_sizes, int n_in,
                              void* d_out, int out_size)
{
    const int*   dec_input  = (const int*)  d_in[0];
    const float* dec_hidden = (const float*)d_in[1];
    const float* enc_output = (const float*)d_in[2];
    const int*   dec_target = (const int*)  d_in[3];
    const float* embedding  = (const float*)d_in[4];
    const float* W1  = (const float*)d_in[5];
    const float* W2  = (const float*)d_in[6];
    const float* v_a = (const float*)d_in[7];
    const float* Wx  = (const float*)d_in[8];
    const float* Wh  = (const float*)d_in[9];
    const float* b_g = (const float*)d_in[10];
    const float* Wo  = (const float*)d_in[11];
    const float* bo  = (const float*)d_in[12];
    float* out = (float*)d_out;

    // Precompute: encW1 = enc @ W1 (4096x512, K=512)
    gemm_k<0><<<dim3(4, 32), 256>>>(enc_output, W1, Wx, nullptr, nullptr,
                                    nullptr, nullptr, nullptr, nullptr,
                                    4096, 512);
    // Precompute: gxemb = emb[tok] @ Wx_bot + b_g (2016x1536, K=256)
    gemm_k<1><<<dim3(12, 16), 256>>>(nullptr, nullptr, Wx, nullptr, b_g,
                                     dec_input, dec_target, embedding, nullptr,
                                     2016, 256);
    // Initial attention context from dec_hidden
    k_hw2<<<dim3(4, 4), 256>>>(dec_hidden, W2, -1);
    k_score<<<dim3(16, 32), 256>>>(v_a);
    k_softctx<<<dim3(4, 32), 256>>>(enc_output);

    // Recurrence: 63 steps
    for (int t = 0; t < NSTEP; t++) {
        k_comb <<<dim3(4, 20), 256>>>(dec_hidden, Wx, Wh, t);
        k_hh3  <<<dim3(4, 4), 256>>>(dec_hidden, Wh, t);
        k_blend<<<32, 512>>>(dec_hidden, t);
        if (t < NSTEP - 1) {
            k_hw2<<<dim3(4, 4), 256>>>(dec_hidden, W2, t);
            k_score<<<dim3(16, 32), 256>>>(v_a);
            k_softctx<<<dim3(4, 32), 256>>>(enc_output);
        }
    }
    // Deferred pred GEMM (2016x32000, K=512)
    gemm_k<2><<<dim3(250, 16), 256>>>(nullptr, nullptr, nullptr, Wo, bo,
                                      nullptr, nullptr, nullptr, out,
                                      2016, 512);
    if ((long long)out_size >= OUT_PRED + BB * HH)
        k_copyh<<<64, 256>>>(out + OUT_PRED);
}

// round 10
// speedup vs baseline: 1.3841x; 1.1905x over previous
#include <cuda_runtime.h>
#include <cuda_bf16.h>

// Problem constants
#define BV     32000
#define EE     256
#define HH     512
#define SS     128
#define TT     64
#define BB     32
#define NSTEP  63
#define H3     1536
#define OUT_PRED (64512000LL)
#define NB     128     // persistent blocks (<=148 SMs, all resident)

// ---------------- scratch ----------------------------------------------------
__device__ float g_encCat[4096 * 2048];   // [b*128+s][0:512)=enc@W1, [512:2048)=enc@Wx_top
__device__ float g_gxemb [NSTEP * BB * H3];
__device__ float g_h     [NSTEP * BB * HH];
__device__ float g_score [BB * SS];
__device__ float g_p1    [4 * BB * 1536]; // proj partials: cols 0..1023 h@Wh_zr, 1024..1535 h@W2
__device__ float g_ph    [4 * BB * HH];   // rh@Wh3 partials
__device__ float g_z     [BB * HH];
__device__ float g_rh    [BB * HH];
__device__ float g_gx3   [BB * HH];

// ---------------- helpers ----------------------------------------------------
__device__ __forceinline__ unsigned long long dup2(float b) {
    unsigned long long r;
    unsigned int u = __float_as_uint(b);
    asm("mov.b64 %0, {%1, %1};" : "=l"(r) : "r"(u));
    return r;
}
__device__ __forceinline__ void fma2(unsigned long long& d,
                                     unsigned long long a,
                                     unsigned long long b) {
    asm("fma.rn.f32x2 %0, %1, %2, %3;" : "=l"(d) : "l"(a), "l"(b), "l"(d));
}
__device__ __forceinline__ float fast_tanh(float x) {
    float e = __expf(2.0f * x);
    return 1.0f - 2.0f / (e + 1.0f);
}
__device__ __forceinline__ float fast_sig(float x) {
    return 1.0f / (1.0f + __expf(-x));
}
__device__ __forceinline__ float tanh_approx(float x) {
    float y;
    asm("tanh.approx.f32 %0, %1;" : "=f"(y) : "f"(x));
    return y;
}
__device__ __forceinline__ float p1s(int b, int col) {
    return g_p1[(0 * BB + b) * 1536 + col] + g_p1[(1 * BB + b) * 1536 + col]
         + g_p1[(2 * BB + b) * 1536 + col] + g_p1[(3 * BB + b) * 1536 + col];
}

// ---------------- grid barrier (all NB blocks resident) ----------------------
__device__ unsigned int g_cnt = 0;
__device__ volatile unsigned int g_gen = 0;
__device__ __forceinline__ void gbar() {
    __syncthreads();
    if (threadIdx.x == 0) {
        unsigned int gen = g_gen;
        __threadfence();
        unsigned int a = atomicAdd(&g_cnt, 1u);
        if (a == NB - 1) {
            atomicExch(&g_cnt, 0u);
            __threadfence();
            atomicAdd((unsigned int*)&g_gen, 1u);
        } else {
            while (g_gen == gen) { }
            __threadfence();
        }
    }
    __syncthreads();
}

// ---------------- generic 128x128 tiled fp32 GEMM ----------------------------
// MODE 0: C=g_encCat : A=enc(4096x512),         B=[W1 | Wx_top](512x2048)
// MODE 1: C=g_gxemb  : A=emb[tok(m)](2016x256), B=Wx_bot(256x1536), +b_g
// MODE 2: C=preds    : A=g_h(2016x512),         B=Wo(512x32000), +bo, scatter
template<int MODE>
__global__ __launch_bounds__(256, 2)
void gemm_k(const float* __restrict__ A,  const float* __restrict__ W1,
            const float* __restrict__ Wx, const float* __restrict__ Wo,
            const float* __restrict__ bias,
            const int*   __restrict__ dinp, const int* __restrict__ dtgt,
            const float* __restrict__ emb, float* __restrict__ C,
            int M, int K)
{
    __shared__ __align__(16) float As[16][132];
    __shared__ __align__(16) float Bs[16][132];

    const int tid = threadIdx.x;
    const int tx = tid & 15;
    const int ty = tid >> 4;
    const int bn = blockIdx.x, bm = blockIdx.y;

    unsigned long long acc[4][8];
#pragma unroll
    for (int i = 0; i < 4; i++)
#pragma unroll
        for (int j = 0; j < 8; j++) acc[i][j] = 0ULL;

    const int nTiles = K >> 4;
    for (int kt = 0; kt < nTiles; ++kt) {
#pragma unroll
        for (int q = 0; q < 2; q++) {
            int l = tid * 2 + q;
            int r = l >> 2;
            int cseg = l & 3;
            int rowg = bm * 128 + r; if (rowg > M - 1) rowg = M - 1;
            const float* ap;
            if (MODE == 1) {
                int t = rowg >> 5, b = rowg & 31;
                int tok = (t == 0) ? dinp[b] : dtgt[b * TT + t];
                ap = emb + (long long)tok * EE;
            } else if (MODE == 2) {
                ap = g_h + (long long)rowg * HH;
            } else {
                ap = A + (long long)rowg * K;
            }
            float4 v = *reinterpret_cast<const float4*>(ap + kt * 16 + cseg * 4);
            As[cseg * 4 + 0][r] = v.x; As[cseg * 4 + 1][r] = v.y;
            As[cseg * 4 + 2][r] = v.z; As[cseg * 4 + 3][r] = v.w;
            int kr = l >> 5;
            int nseg = l & 31;
            int kg = kt * 16 + kr;
            int n = bn * 128 + nseg * 4;
            const float* bp;
            if (MODE == 0) {
                bp = (n < 512) ? (W1 + (long long)kg * 512 + n)
                               : (Wx + (long long)kg * H3 + (n - 512));
            } else if (MODE == 1) {
                bp = Wx + (long long)(512 + kg) * H3 + n;
            } else {
                bp = Wo + (long long)kg * BV + n;
            }
            *reinterpret_cast<float4*>(&Bs[kr][nseg * 4]) =
                *reinterpret_cast<const float4*>(bp);
        }
        __syncthreads();
#pragma unroll
        for (int k = 0; k < 16; k++) {
            const unsigned long long* arow =
                reinterpret_cast<const unsigned long long*>(&As[k][0]);
            unsigned long long a0 = arow[ty * 4 + 0];
            unsigned long long a1 = arow[ty * 4 + 1];
            unsigned long long a2 = arow[ty * 4 + 2];
            unsigned long long a3 = arow[ty * 4 + 3];
            float4 b0 = *reinterpret_cast<const float4*>(&Bs[k][tx * 4]);
            float4 b1 = *reinterpret_cast<const float4*>(&Bs[k][64 + tx * 4]);
            float bf[8] = {b0.x, b0.y, b0.z, b0.w, b1.x, b1.y, b1.z, b1.w};
#pragma unroll
            for (int j = 0; j < 8; j++) {
                unsigned long long dj = dup2(bf[j]);
                fma2(acc[0][j], a0, dj);
                fma2(acc[1][j], a1, dj);
                fma2(acc[2][j], a2, dj);
                fma2(acc[3][j], a3, dj);
            }
        }
        __syncthreads();
    }

    const int nA = bn * 128 + tx * 4;
    const int nB2 = nA + 64;
#pragma unroll
    for (int i2 = 0; i2 < 4; i2++) {
#pragma unroll
        for (int p = 0; p < 2; p++) {
            int m = bm * 128 + ty * 8 + i2 * 2 + p;
            if (m >= M) continue;
            float vals[8];
#pragma unroll
            for (int j = 0; j < 8; j++) {
                unsigned long long u = acc[i2][j];
                unsigned int w = (p == 0) ? (unsigned int)u
                                          : (unsigned int)(u >> 32);
                vals[j] = __uint_as_float(w);
            }
            if (MODE == 0) {
                float* cp = g_encCat + (long long)m * 2048;
                *reinterpret_cast<float4*>(cp + nA) =
                    make_float4(vals[0], vals[1], vals[2], vals[3]);
                *reinterpret_cast<float4*>(cp + nB2) =
                    make_float4(vals[4], vals[5], vals[6], vals[7]);
            } else if (MODE == 1) {
                float* cp = g_gxemb + (long long)m * H3;
                float4 ba = *reinterpret_cast<const float4*>(bias + nA);
                float4 bb = *reinterpret_cast<const float4*>(bias + nB2);
                *reinterpret_cast<float4*>(cp + nA) =
                    make_float4(vals[0] + ba.x, vals[1] + ba.y,
                                vals[2] + ba.z, vals[3] + ba.w);
                *reinterpret_cast<float4*>(cp + nB2) =
                    make_float4(vals[4] + bb.x, vals[5] + bb.y,
                                vals[6] + bb.z, vals[7] + bb.w);
            } else {
                int t = m >> 5, b = m & 31;
                float* cp = C + (long long)b * (NSTEP * (long long)BV)
                              + (long long)t * BV;
                float4 ba = *reinterpret_cast<const float4*>(bias + nA);
                float4 bb = *reinterpret_cast<const float4*>(bias + nB2);
                *reinterpret_cast<float4*>(cp + nA) =
                    make_float4(vals[0] + ba.x, vals[1] + ba.y,
                                vals[2] + ba.z, vals[3] + ba.w);
                *reinterpret_cast<float4*>(cp + nB2) =
                    make_float4(vals[4] + bb.x, vals[5] + bb.y,
                                vals[6] + bb.z, vals[7] + bb.w);
            }
        }
    }
}

// ---------------- persistent recurrence: 5 phases/step, one launch -----------
__global__ __launch_bounds__(256)
void k_recur(const float* __restrict__ dec_hidden,
             const float* __restrict__ W2,
             const float* __restrict__ Wh,
             const float* __restrict__ v_a)
{
    const int bid = blockIdx.x;
    const int tid = threadIdx.x;
    __shared__ float sh[4352];    // union: hT[128*34] | {hv,vv} | {at,red}

    for (int t = 0; t < NSTEP; t++) {
        const float* hprev = (t == 0) ? dec_hidden
                                      : g_h + (long long)(t - 1) * BB * HH;

        // ---- P1 (48 blocks): partials of h_prev @ [Wh_zr(1024) | W2(512)]
        if (bid < 48) {
            const int kc = bid & 3, bc = bid >> 2;
            const int kbase = kc * 128;
            for (int i = tid; i < 4096; i += 256) {
                int b = i >> 7, k = i & 127;
                sh[k * 34 + b] = hprev[b * HH + kbase + k];
            }
            __syncthreads();
            const int cq = tid & 31, bq = tid >> 5;
            const int c0 = bc * 128 + cq * 4;
            const float* wrow; int ldw;
            if (c0 < 1024) { wrow = Wh + c0;          ldw = H3;  }
            else           { wrow = W2 + (c0 - 1024); ldw = 512; }

            unsigned long long acc[4][2];
#pragma unroll
            for (int c = 0; c < 4; c++) { acc[c][0] = 0ULL; acc[c][1] = 0ULL; }
#pragma unroll 4
            for (int k = 0; k < 128; k++) {
                float4 w = *reinterpret_cast<const float4*>(
                    wrow + (long long)(kbase + k) * ldw);
                unsigned long long h01 = *reinterpret_cast<const unsigned long long*>(
                    &sh[k * 34 + bq * 4]);
                unsigned long long h23 = *reinterpret_cast<const unsigned long long*>(
                    &sh[k * 34 + bq * 4 + 2]);
                unsigned long long w0 = dup2(w.x), w1 = dup2(w.y),
                                   w2 = dup2(w.z), w3 = dup2(w.w);
                fma2(acc[0][0], h01, w0); fma2(acc[0][1], h23, w0);
                fma2(acc[1][0], h01, w1); fma2(acc[1][1], h23, w1);
                fma2(acc[2][0], h01, w2); fma2(acc[2][1], h23, w2);
                fma2(acc[3][0], h01, w3); fma2(acc[3][1], h23, w3);
            }
#pragma unroll
            for (int c = 0; c < 4; c++)
#pragma unroll
                for (int p = 0; p < 2; p++) {
                    int b = bq * 4 + p * 2;
                    unsigned long long u = acc[c][p];
                    g_p1[(kc * BB + b)     * 1536 + c0 + c] =
                        __uint_as_float((unsigned int)u);
                    g_p1[(kc * BB + b + 1) * 1536 + c0 + c] =
                        __uint_as_float((unsigned int)(u >> 32));
                }
        }
        gbar();

        // ---- P2 (128 blocks): scores. b=bid&31, sc=bid>>5 (32 s each)
        {
            const int b = bid & 31, sc = bid >> 5;
            for (int i = tid; i < HH; i += 256) {
                sh[i] = p1s(b, 1024 + i);   // hW2
                sh[512 + i] = v_a[i];
            }
            __syncthreads();
            const int warp = tid >> 5, lane = tid & 31;
#pragma unroll
            for (int j = 0; j < 4; j++) {
                int s = sc * 32 + j * 8 + warp;
                const float* e = g_encCat + (long long)(b * SS + s) * 2048;
                float sum = 0.f;
#pragma unroll
                for (int i = 0; i < 16; i++) {
                    int a = i * 32 + lane;
                    sum += tanh_approx(e[a] + sh[a]) * sh[512 + a];
                }
#pragma unroll
                for (int o = 16; o > 0; o >>= 1)
                    sum += __shfl_xor_sync(0xffffffffu, sum, o);
                if (lane == 0) g_score[b * SS + s] = sum;
            }
        }
        gbar();

        // ---- P3 (128 blocks): softmax + gx mix + gates. b=bid&31, jc=bid>>5
        {
            const int b = bid & 31, jc = bid >> 5;
            float scv = (tid < SS) ? g_score[b * SS + tid] : -1e30f;
            if (tid < SS) sh[128 + tid] = scv;
            __syncthreads();
            for (int o = 64; o > 0; o >>= 1) {
                if (tid < o) sh[128 + tid] = fmaxf(sh[128 + tid], sh[128 + tid + o]);
                __syncthreads();
            }
            float mx = sh[128];
            __syncthreads();
            if (tid < SS) sh[128 + tid] = __expf(scv - mx);
            __syncthreads();
            for (int o = 64; o > 0; o >>= 1) {
                if (tid < o) sh[128 + tid] += sh[128 + tid + o];
                __syncthreads();
            }
            float ssum = sh[128];
            __syncthreads();
            if (tid < SS) sh[tid] = __expf(scv - mx) / ssum;   // at[]
            __syncthreads();

            const float* ge = g_gxemb + ((long long)t * BB + b) * H3;
            for (int jj = tid; jj < 384; jj += 256) {
                int j = jc * 384 + jj;
                const float* e = g_encCat + (long long)b * SS * 2048 + 512 + j;
                float acc = 0.f;
#pragma unroll 8
                for (int s = 0; s < SS; s++) acc += sh[s] * e[(long long)s * 2048];
                acc += ge[j];
                if (j < 512) {
                    g_z[b * HH + j] = fast_sig(acc + p1s(b, j));
                } else if (j < 1024) {
                    int c = j - 512;
                    float r = fast_sig(acc + p1s(b, j));
                    g_rh[b * HH + c] = r * hprev[b * HH + c];
                } else {
                    g_gx3[b * HH + (j - 1024)] = acc;
                }
            }
        }
        gbar();

        // ---- P4 (16 blocks): rh @ Wh[:,1024:] partials
        if (bid < 16) {
            const int kc = bid & 3, bc = bid >> 2;
            const int kbase = kc * 128;
            for (int i = tid; i < 4096; i += 256) {
                int b = i >> 7, k = i & 127;
                sh[k * 34 + b] = g_rh[b * HH + kbase + k];
            }
            __syncthreads();
            const int cq = tid & 31, bq = tid >> 5;
            const int c0 = bc * 128 + cq * 4;
            const float* wrow = Wh + 1024 + c0;

            unsigned long long acc[4][2];
#pragma unroll
            for (int c = 0; c < 4; c++) { acc[c][0] = 0ULL; acc[c][1] = 0ULL; }
#pragma unroll 4
            for (int k = 0; k < 128; k++) {
                float4 w = *reinterpret_cast<const float4*>(
                    wrow + (long long)(kbase + k) * H3);
                unsigned long long h01 = *reinterpret_cast<const unsigned long long*>(
                    &sh[k * 34 + bq * 4]);
                unsigned long long h23 = *reinterpret_cast<const unsigned long long*>(
                    &sh[k * 34 + bq * 4 + 2]);
                unsigned long long w0 = dup2(w.x), w1 = dup2(w.y),
                                   w2 = dup2(w.z), w3 = dup2(w.w);
                fma2(acc[0][0], h01, w0); fma2(acc[0][1], h23, w0);
                fma2(acc[1][0], h01, w1); fma2(acc[1][1], h23, w1);
                fma2(acc[2][0], h01, w2); fma2(acc[2][1], h23, w2);
                fma2(acc[3][0], h01, w3); fma2(acc[3][1], h23, w3);
            }
#pragma unroll
            for (int c = 0; c < 4; c++)
#pragma unroll
                for (int p = 0; p < 2; p++) {
                    int b = bq * 4 + p * 2;
                    unsigned long long u = acc[c][p];
                    g_ph[(kc * BB + b)     * HH + c0 + c] =
                        __uint_as_float((unsigned int)u);
                    g_ph[(kc * BB + b + 1) * HH + c0 + c] =
                        __uint_as_float((unsigned int)(u >> 32));
                }
        }
        gbar();

        // ---- P5 (32 blocks): candidate tanh + blend -> h_t
        if (bid < 32) {
            const int b = bid;
            for (int c = tid; c < HH; c += 256) {
                float hs = g_ph[(0 * BB + b) * HH + c] + g_ph[(1 * BB + b) * HH + c]
                         + g_ph[(2 * BB + b) * HH + c] + g_ph[(3 * BB + b) * HH + c];
                float hh = fast_tanh(g_gx3[b * HH + c] + hs);
                float z  = g_z[b * HH + c];
                float hp = hprev[b * HH + c];
                g_h[((long long)t * BB + b) * HH + c] = z * hp + (1.f - z) * hh;
            }
        }
        if (t < NSTEP - 1) gbar();
    }
}

// final hidden state copy
__global__ void k_copyh(float* __restrict__ out)
{
    int i = blockIdx.x * 256 + threadIdx.x;
    out[i] = g_h[(long long)(NSTEP - 1) * BB * HH + i];
}

extern "C" void kernel_launch(void* const* d_in, const int* in_sizes, int n_in,
                              void* d_out, int out_size)
{
    const int*   dec_input  = (const int*)  d_in[0];
    const float* dec_hidden = (const float*)d_in[1];
    const float* enc_output = (const float*)d_in[2];
    const int*   dec_target = (const int*)  d_in[3];
    const float* embedding  = (const float*)d_in[4];
    const float* W1  = (const float*)d_in[5];
    const float* W2  = (const float*)d_in[6];
    const float* v_a = (const float*)d_in[7];
    const float* Wx  = (const float*)d_in[8];
    const float* Wh  = (const float*)d_in[9];
    const float* b_g = (const float*)d_in[10];
    const float* Wo  = (const float*)d_in[11];
    const float* bo  = (const float*)d_in[12];
    float* out = (float*)d_out;

    // Precompute: encCat = enc @ [W1 | Wx_top]   (4096 x 2048, K=512)
    gemm_k<0><<<dim3(16, 32), 256>>>(enc_output, W1, Wx, nullptr, nullptr,
                                     nullptr, nullptr, nullptr, nullptr,
                                     4096, 512);
    // Precompute: gxemb = emb[tok] @ Wx_bot + b_g (2016 x 1536, K=256)
    gemm_k<1><<<dim3(12, 16), 256>>>(nullptr, nullptr, Wx, nullptr, b_g,
                                     dec_input, dec_target, embedding, nullptr,
                                     2016, 256);
    // Persistent recurrence: 63 steps, ONE launch
    k_recur<<<NB, 256>>>(dec_hidden, W2, Wh, v_a);
    // Deferred pred GEMM (2016 x 32000, K=512)
    gemm_k<2><<<dim3(250, 16), 256>>>(nullptr, nullptr, nullptr, Wo, bo,
                                      nullptr, nullptr, nullptr, out,
                                      2016, 512);
    if ((long long)out_size >= OUT_PRED + BB * HH)
        k_copyh<<<64, 256>>>(out + OUT_PRED);
}